// round 3
// baseline (speedup 1.0000x reference)
#include <cuda_runtime.h>
#include <math.h>

#define HW   400
#define LCH  9
#define BS   2
#define CD   1024
#define CH   256
#define NLB  18          // L*B batches
#define TEMP 20.0f

// ---------------- scratch (device globals; no runtime allocation) ----------------
__device__ float g_sumsq[2 * NLB * HW];
__device__ float g_invn [2 * NLB * HW];
__device__ float g_corrA[(size_t)2 * NLB * HW * HW];   // [branch(2)][b][l][ij][km]
__device__ float g_buf1 [(size_t)4 * 10 * HW * HW];
__device__ float g_buf2 [(size_t)4 * 10 * HW * HW];
__device__ float g_c4ab [4 * HW * HW];
__device__ float g_c4   [BS * HW * HW];
__device__ float g_attn [BS * HW * HW];
__device__ float g_nrm  [2 * BS * HW];

// ---------------- f32x2 packed-FMA helpers (FFMA2) ----------------
__device__ __forceinline__ unsigned long long pack2(float x, float y) {
    unsigned long long r;
    asm("mov.b64 %0, {%1, %2};" : "=l"(r) : "f"(x), "f"(y));
    return r;
}
__device__ __forceinline__ void unpack2(unsigned long long v, float& x, float& y) {
    asm("mov.b64 {%0, %1}, %2;" : "=f"(x), "=f"(y) : "l"(v));
}
__device__ __forceinline__ void fma2(unsigned long long& d, unsigned long long a,
                                     unsigned long long b) {
    asm("fma.rn.f32x2 %0, %1, %2, %0;" : "+l"(d) : "l"(a), "l"(b));
}

// ---------------- utility ----------------
__global__ void zero_k(float* p, int n) {
    int i = blockIdx.x * blockDim.x + threadIdx.x;
    if (i < n) p[i] = 0.f;
}

__global__ void sumsq_k(const float* __restrict__ fq, const float* __restrict__ fs,
                        float* __restrict__ out) {
    int z  = blockIdx.z;
    int lb = blockIdx.x;
    int c0 = blockIdx.y * 64;
    int pos = threadIdx.x;
    const float* x = (z ? fs : fq) + ((size_t)lb * CD + c0) * HW + pos;
    float s = 0.f;
    #pragma unroll 8
    for (int c = 0; c < 64; c++) {
        float v = x[(size_t)c * HW];
        s += v * v;
    }
    atomicAdd(&out[z * NLB * HW + lb * HW + pos], s);
}

__global__ void invn_k(const float* __restrict__ s, float* __restrict__ inv, int n) {
    int i = blockIdx.x * blockDim.x + threadIdx.x;
    if (i < n) inv[i] = 1.f / fmaxf(sqrtf(s[i]), 1e-12f);
}

// ---------------- correlation GEMM (TN), FFMA2 ----------------
// grid (2, 4, 18), block 400: tile 100(rows=ij) x 200(cols=km), K-tile 16.
// Thread = 5 strided rows x 10 contiguous cols (5 float2).
__global__ void __launch_bounds__(400) corr_gemm_k(
        const float* __restrict__ fq, const float* __restrict__ fs,
        const float* __restrict__ invn, float* __restrict__ corr) {
    int lb = blockIdx.z;
    const float* A  = fq + (size_t)lb * CD * HW;
    const float* Bm = fs + (size_t)lb * CD * HW;
    int ij0 = blockIdx.y * 100, km0 = blockIdx.x * 200;

    __shared__ float As[16][100];
    __shared__ float Bs[16][200];
    int tid = threadIdx.x;
    int tx = tid % 20, ty = tid / 20;

    unsigned long long acc[5][5];
    #pragma unroll
    for (int r = 0; r < 5; r++)
        #pragma unroll
        for (int s = 0; s < 5; s++) acc[r][s] = 0ull;

    for (int c0 = 0; c0 < CD; c0 += 16) {
        // stage A: 400 float4 (1/thread), B: 800 float4 (2/thread)
        {
            int ka = tid / 25, va = tid % 25;
            *(float4*)&As[ka][va * 4] =
                *(const float4*)(A + (size_t)(c0 + ka) * HW + ij0 + va * 4);
            #pragma unroll
            for (int u = 0; u < 2; u++) {
                int t2 = tid + u * 400;
                int kb = t2 / 50, vb = t2 % 50;
                *(float4*)&Bs[kb][vb * 4] =
                    *(const float4*)(Bm + (size_t)(c0 + kb) * HW + km0 + vb * 4);
            }
        }
        __syncthreads();
        #pragma unroll
        for (int kk = 0; kk < 16; kk++) {
            unsigned long long a[5], b[5];
            #pragma unroll
            for (int r = 0; r < 5; r++) {
                float av = As[kk][r * 20 + ty];
                a[r] = pack2(av, av);
            }
            #pragma unroll
            for (int s = 0; s < 5; s++)
                b[s] = *(const unsigned long long*)&Bs[kk][tx * 10 + 2 * s];
            #pragma unroll
            for (int r = 0; r < 5; r++)
                #pragma unroll
                for (int s = 0; s < 5; s++) fma2(acc[r][s], a[r], b[s]);
        }
        __syncthreads();
    }

    int b = lb & 1, l = lb >> 1;
    const float* iq = invn + (size_t)lb * HW;
    const float* is = invn + NLB * HW + (size_t)lb * HW;
    float* cp = corr + (size_t)(b * LCH + l) * HW * HW;
    #pragma unroll
    for (int r = 0; r < 5; r++) {
        int ij = ij0 + r * 20 + ty;
        float sq = iq[ij];
        #pragma unroll
        for (int s = 0; s < 5; s++) {
            int col = km0 + tx * 10 + 2 * s;
            float2 isv = *(const float2*)&is[col];
            float lo, hi;
            unpack2(acc[r][s], lo, hi);
            float2 o;
            o.x = lo * sq * isv.x;
            o.y = hi * sq * isv.y;
            *(float2*)&cp[(size_t)ij * HW + col] = o;
        }
    }
}

// ---------------- 4D conv layer (3x3x3x3, pad 1, relu) ----------------
// Block per (bb,i,j) with bb in [0,4) (branches merged as batch).
// Thread = (co, PKxPM patch). All weights staged once; per-ci plane staging.
template <int CIN, int COUT, int PK, int PM>
__global__ void __launch_bounds__(400 / (PK * PM) * COUT) conv4d_k(
        const float* __restrict__ x, const float* __restrict__ wt,
        float* __restrict__ y) {
    constexpr int NPATCH   = 400 / (PK * PM);
    constexpr int NTHREADS = NPATCH * COUT;
    constexpr int NPM      = 20 / PM;

    __shared__ float sp[9 * 484];
    __shared__ float wAll[CIN * 81 * COUT];

    int bij = blockIdx.x;
    int bb = bij / HW, ij = bij % HW;
    int i = ij / 20, j = ij % 20;
    int tid = threadIdx.x;
    int g   = tid / NPATCH;
    int pid = tid % NPATCH;
    int k0 = (pid / NPM) * PK;
    int m0 = (pid % NPM) * PM;

    // stage ALL weights once: wAll[(ci*81+dijtap)*COUT + co] = wt[co][ci][dijtap]
    for (int t = tid; t < CIN * 81 * COUT; t += NTHREADS) {
        int co = t % COUT, rem = t / COUT;
        wAll[t] = wt[(size_t)co * CIN * 81 + rem];
    }
    // zero pad ring once
    for (int t = tid; t < 9 * 484; t += NTHREADS) sp[t] = 0.f;

    float acc[PK][PM];
    #pragma unroll
    for (int pk = 0; pk < PK; pk++)
        #pragma unroll
        for (int pm = 0; pm < PM; pm++) acc[pk][pm] = 0.f;

    for (int ci = 0; ci < CIN; ci++) {
        __syncthreads();
        for (int t = tid; t < 9 * 400; t += NTHREADS) {
            int p = t / 400, rem = t % 400;
            int di = p / 3, dj = p % 3;
            int ii = i + di - 1, jj = j + dj - 1;
            bool v = ((unsigned)ii < 20u) && ((unsigned)jj < 20u);
            float val = v ? x[((size_t)(bb * CIN + ci) * 400 + ii * 20 + jj) * 400 + rem] : 0.f;
            int r = rem / 20, c = rem % 20;
            sp[p * 484 + (r + 1) * 22 + (c + 1)] = val;
        }
        __syncthreads();

        #pragma unroll
        for (int dij = 0; dij < 9; dij++) {
            const float* P = sp + dij * 484 + k0 * 22 + m0;
            float xin[PK + 2][PM + 2];
            #pragma unroll
            for (int r = 0; r < PK + 2; r++)
                #pragma unroll
                for (int c = 0; c < PM + 2; c++) xin[r][c] = P[r * 22 + c];

            const float* wp = wAll + (ci * 81 + dij * 9) * COUT + g;
            #pragma unroll
            for (int dk = 0; dk < 3; dk++)
                #pragma unroll
                for (int dm = 0; dm < 3; dm++) {
                    float w = wp[(dk * 3 + dm) * COUT];
                    #pragma unroll
                    for (int pk = 0; pk < PK; pk++)
                        #pragma unroll
                        for (int pm = 0; pm < PM; pm++)
                            acc[pk][pm] += xin[pk + dk][pm + dm] * w;
                }
        }
    }

    float* yp = y + ((size_t)(bb * COUT + g) * 400 + ij) * 400;
    #pragma unroll
    for (int pk = 0; pk < PK; pk++)
        #pragma unroll
        for (int pm = 0; pm < PM; pm++)
            yp[(k0 + pk) * 20 + (m0 + pm)] = fmaxf(acc[pk][pm], 0.f);
}

// ---------------- tiled transpose: corrA plane m -> plane 18+m ----------------
__global__ void transpose_k(const float* __restrict__ in, float* __restrict__ out) {
    __shared__ float t[32][33];
    int mtx = blockIdx.z;
    const float* A = in  + (size_t)mtx * HW * HW;
    float*       O = out + (size_t)mtx * HW * HW;
    int x0 = blockIdx.x * 32, y0 = blockIdx.y * 32;
    int tx = threadIdx.x, ty = threadIdx.y;
    #pragma unroll
    for (int r = 0; r < 32; r += 8) {
        int yy = y0 + ty + r, xx = x0 + tx;
        t[ty + r][tx] = (yy < HW && xx < HW) ? A[(size_t)yy * HW + xx] : 0.f;
    }
    __syncthreads();
    #pragma unroll
    for (int r = 0; r < 32; r += 8) {
        int yy = x0 + ty + r, xx = y0 + tx;
        if (yy < HW && xx < HW) O[(size_t)yy * HW + xx] = t[tx][ty + r];
    }
}

// c4[b][q][s] = a[b][q][s] + bt[b][s][q]
__global__ void addt_k(const float* __restrict__ a, const float* __restrict__ bt,
                       float* __restrict__ o) {
    __shared__ float t[32][33];
    int b = blockIdx.z;
    const float* A  = a  + (size_t)b * HW * HW;
    const float* Bt = bt + (size_t)b * HW * HW;
    float*       O  = o  + (size_t)b * HW * HW;
    int q0 = blockIdx.y * 32, s0 = blockIdx.x * 32;
    int tx = threadIdx.x, ty = threadIdx.y;
    #pragma unroll
    for (int r = 0; r < 32; r += 8) {
        int s = s0 + ty + r, q = q0 + tx;
        t[ty + r][tx] = (s < HW && q < HW) ? Bt[(size_t)s * HW + q] : 0.f;
    }
    __syncthreads();
    #pragma unroll
    for (int r = 0; r < 32; r += 8) {
        int q = q0 + ty + r, s = s0 + tx;
        if (q < HW && s < HW) O[(size_t)q * HW + s] = A[(size_t)q * HW + s] + t[tx][ty + r];
    }
}

// ---------------- softmax over rows of c4*TEMP ----------------
__global__ void softmax_k(const float* __restrict__ x, float* __restrict__ y) {
    int row = blockIdx.x;
    const float* xr = x + (size_t)row * HW;
    float*       yr = y + (size_t)row * HW;
    __shared__ float sh[HW];
    __shared__ float red[4];
    int tid = threadIdx.x;
    float mx = -3.4e38f;
    for (int i = tid; i < HW; i += 128) {
        float v = xr[i] * TEMP;
        sh[i] = v;
        mx = fmaxf(mx, v);
    }
    #pragma unroll
    for (int o = 16; o; o >>= 1) mx = fmaxf(mx, __shfl_xor_sync(0xffffffffu, mx, o));
    if ((tid & 31) == 0) red[tid >> 5] = mx;
    __syncthreads();
    mx = fmaxf(fmaxf(red[0], red[1]), fmaxf(red[2], red[3]));
    float sum = 0.f;
    for (int i = tid; i < HW; i += 128) {
        float e = expf(sh[i] - mx);
        sh[i] = e;
        sum += e;
    }
    #pragma unroll
    for (int o = 16; o; o >>= 1) sum += __shfl_xor_sync(0xffffffffu, sum, o);
    __syncthreads();
    if ((tid & 31) == 0) red[tid >> 5] = sum;
    __syncthreads();
    float inv = 1.f / (red[0] + red[1] + red[2] + red[3]);
    for (int i = tid; i < HW; i += 128) yr[i] = sh[i] * inv;
}

// ---------------- attention GEMM (NT): out[b][c][q] = sum_s v[c][s] * attn[q][s]
__global__ void attn_gemm_k(const float* __restrict__ attn, const float* __restrict__ v,
                            float* __restrict__ out) {
    int b = blockIdx.z;
    const float* A = v    + (size_t)b * CH * HW;
    const float* P = attn + (size_t)b * HW * HW;
    int c0 = blockIdx.y * 64, q0 = blockIdx.x * 64;

    __shared__ float As[16][65];
    __shared__ float Ps[16][65];
    int tid = threadIdx.x;
    int tx = tid & 15, ty = tid >> 4;
    float acc[4][4] = {};

    for (int s0 = 0; s0 < HW; s0 += 16) {
        #pragma unroll
        for (int t = tid; t < 1024; t += 256) {
            int row = t >> 4, kk = t & 15;
            int c = c0 + row, q = q0 + row;
            As[kk][row] = (c < CH) ? A[(size_t)c * HW + s0 + kk] : 0.f;
            Ps[kk][row] = (q < HW) ? P[(size_t)q * HW + s0 + kk] : 0.f;
        }
        __syncthreads();
        #pragma unroll
        for (int kk = 0; kk < 16; kk++) {
            float a[4], p[4];
            #pragma unroll
            for (int r = 0; r < 4; r++) { a[r] = As[kk][ty * 4 + r]; p[r] = Ps[kk][tx * 4 + r]; }
            #pragma unroll
            for (int r = 0; r < 4; r++)
                #pragma unroll
                for (int s = 0; s < 4; s++) acc[r][s] += a[r] * p[s];
        }
        __syncthreads();
    }
    #pragma unroll
    for (int r = 0; r < 4; r++) {
        int c = c0 + ty * 4 + r;
        if (c >= CH) continue;
        #pragma unroll
        for (int s = 0; s < 4; s++) {
            int q = q0 + tx * 4 + s;
            if (q < HW) out[((size_t)b * CH + c) * HW + q] = acc[r][s];
        }
    }
}

// ---------------- final norms + combine ----------------
__global__ void norm2_k(const float* __restrict__ fqin, const float* __restrict__ att,
                        float* __restrict__ nrm) {
    int b = blockIdx.x, z = blockIdx.y;
    const float* x = (z ? att : fqin) + (size_t)b * CH * HW + threadIdx.x;
    float s = 0.f;
    #pragma unroll 8
    for (int c = 0; c < CH; c++) {
        float v = x[(size_t)c * HW];
        s += v * v;
    }
    nrm[(z * BS + b) * HW + threadIdx.x] = 1.f / fmaxf(sqrtf(s), 1e-12f);
}

__global__ void combine_k(const float* __restrict__ fqin, const float* __restrict__ att,
                          const float* __restrict__ nrm, float* __restrict__ out) {
    int idx = blockIdx.x * blockDim.x + threadIdx.x;
    if (idx >= BS * CH * HW) return;
    int b = idx / (CH * HW);
    int pos = idx % HW;
    out[idx] = fqin[idx] * nrm[b * HW + pos] + att[idx] * nrm[(BS + b) * HW + pos] * 0.5f;
}

// ---------------- launch ----------------
extern "C" void kernel_launch(void* const* d_in, const int* in_sizes, int n_in,
                              void* d_out, int out_size) {
    const float* fqf = (const float*)d_in[0];
    const float* fsf = (const float*)d_in[1];
    const float* f_q = (const float*)d_in[2];
    const float* f_s = (const float*)d_in[3];
    const float* w1  = (const float*)d_in[4];
    const float* w2  = (const float*)d_in[5];
    const float* w3  = (const float*)d_in[6];
    float* out = (float*)d_out;

    float *sumsq, *invn, *corrA, *buf1, *buf2, *c4ab, *c4, *attn, *nrm;
    cudaGetSymbolAddress((void**)&sumsq, g_sumsq);
    cudaGetSymbolAddress((void**)&invn,  g_invn);
    cudaGetSymbolAddress((void**)&corrA, g_corrA);
    cudaGetSymbolAddress((void**)&buf1,  g_buf1);
    cudaGetSymbolAddress((void**)&buf2,  g_buf2);
    cudaGetSymbolAddress((void**)&c4ab,  g_c4ab);
    cudaGetSymbolAddress((void**)&c4,    g_c4);
    cudaGetSymbolAddress((void**)&attn,  g_attn);
    cudaGetSymbolAddress((void**)&nrm,   g_nrm);

    const int NSUM = 2 * NLB * HW;

    // 1. feature L2 norms (folded into GEMM epilogue)
    zero_k<<<(NSUM + 255) / 256, 256>>>(sumsq, NSUM);
    sumsq_k<<<dim3(NLB, 16, 2), 400>>>(fqf, fsf, sumsq);
    invn_k<<<(NSUM + 255) / 256, 256>>>(sumsq, invn, NSUM);

    // 2. correlation tensor (FFMA2) into planes [0,18)
    corr_gemm_k<<<dim3(2, 4, NLB), 400>>>(fqf, fsf, invn, corrA);

    // 3. transposed copies into planes [18,36)
    transpose_k<<<dim3(13, 13, NLB), dim3(32, 8)>>>(corrA, corrA + (size_t)NLB * HW * HW);

    // 4. neighborhood consensus — both branches as batch dim 4
    conv4d_k<9, 10, 5, 5><<<4 * HW, 160>>>(corrA, w1, buf1);
    conv4d_k<10, 10, 5, 5><<<4 * HW, 160>>>(buf1, w2, buf2);
    conv4d_k<10, 1, 5, 1><<<4 * HW, 80>>>(buf2, w3, c4ab);

    // 5. combine branches (B transposed back)
    addt_k<<<dim3(13, 13, BS), dim3(32, 8)>>>(c4ab, c4ab + 2 * HW * HW, c4);

    // 6. softmax + attention
    softmax_k<<<BS * HW, 128>>>(c4, attn);
    attn_gemm_k<<<dim3(7, 4, BS), 256>>>(attn, f_s, out + BS * CH * HW);

    // 7. final L2-norm combine
    norm2_k<<<dim3(BS, 2), 400>>>(f_q, out + BS * CH * HW, nrm);
    combine_k<<<(BS * CH * HW + 255) / 256, 256>>>(f_q, out + BS * CH * HW, nrm, out);
}

// round 4
// speedup vs baseline: 1.6037x; 1.6037x over previous
#include <cuda_runtime.h>
#include <math.h>

#define HW   400
#define LCH  9
#define BS   2
#define CD   1024
#define CH   256
#define NLB  18
#define TEMP 20.0f

typedef unsigned long long u64;

// ---------------- scratch ----------------
__device__ float g_sumsq[2 * NLB * HW];
__device__ float g_invn [2 * NLB * HW];
__device__ float g_corrA[(size_t)2 * NLB * HW * HW];   // [branch(2)][b][l][ij][km]
__device__ float g_buf1 [(size_t)4 * 10 * HW * HW];
__device__ float g_buf2 [(size_t)4 * 10 * HW * HW];
__device__ float g_c4ab [4 * HW * HW];
__device__ float g_c4   [BS * HW * HW];
__device__ float g_attn [BS * HW * HW];
__device__ float g_nrm  [2 * BS * HW];

// ---------------- f32x2 packed-FMA helpers ----------------
__device__ __forceinline__ u64 pack2(float x, float y) {
    u64 r;
    asm("mov.b64 %0, {%1, %2};" : "=l"(r) : "f"(x), "f"(y));
    return r;
}
__device__ __forceinline__ void unpack2(u64 v, float& x, float& y) {
    asm("mov.b64 {%0, %1}, %2;" : "=f"(x), "=f"(y) : "l"(v));
}
__device__ __forceinline__ void fma2(u64& d, u64 a, u64 b) {
    asm("fma.rn.f32x2 %0, %1, %2, %0;" : "+l"(d) : "l"(a), "l"(b));
}

// ---------------- utility ----------------
__global__ void zero_k(float* p, int n) {
    int i = blockIdx.x * blockDim.x + threadIdx.x;
    if (i < n) p[i] = 0.f;
}

__global__ void sumsq_k(const float* __restrict__ fq, const float* __restrict__ fs,
                        float* __restrict__ out) {
    int z  = blockIdx.z;
    int lb = blockIdx.x;
    int c0 = blockIdx.y * 64;
    int pos = threadIdx.x;
    const float* x = (z ? fs : fq) + ((size_t)lb * CD + c0) * HW + pos;
    float s = 0.f;
    #pragma unroll 8
    for (int c = 0; c < 64; c++) {
        float v = x[(size_t)c * HW];
        s += v * v;
    }
    atomicAdd(&out[z * NLB * HW + lb * HW + pos], s);
}

__global__ void invn_k(const float* __restrict__ s, float* __restrict__ inv, int n) {
    int i = blockIdx.x * blockDim.x + threadIdx.x;
    if (i < n) inv[i] = 1.f / fmaxf(sqrtf(s[i]), 1e-12f);
}

// ---------------- correlation GEMM (TN), FFMA2 + register prefetch ----------------
// grid (2, 4, 18), block 400: tile 100 x 200, K-tile 16.
__global__ void __launch_bounds__(400) corr_gemm_k(
        const float* __restrict__ fq, const float* __restrict__ fs,
        const float* __restrict__ invn, float* __restrict__ corr) {
    int lb = blockIdx.z;
    const float* A  = fq + (size_t)lb * CD * HW;
    const float* Bm = fs + (size_t)lb * CD * HW;
    int ij0 = blockIdx.y * 100, km0 = blockIdx.x * 200;

    __shared__ float As[16][100];
    __shared__ float Bs[16][200];
    int tid = threadIdx.x;
    int tx = tid % 20, ty = tid / 20;

    u64 acc[5][5];
    #pragma unroll
    for (int r = 0; r < 5; r++)
        #pragma unroll
        for (int s = 0; s < 5; s++) acc[r][s] = 0ull;

    int ka = tid / 25,  va = (tid % 25) * 4;
    int kb0 = tid / 50, vb0 = (tid % 50) * 4;
    int kb1 = (tid + 400) / 50, vb1 = ((tid + 400) % 50) * 4;
    const float* Ap  = A  + (size_t)ka  * HW + ij0 + va;
    const float* Bp0 = Bm + (size_t)kb0 * HW + km0 + vb0;
    const float* Bp1 = Bm + (size_t)kb1 * HW + km0 + vb1;

    float4 pa  = *(const float4*)Ap;
    float4 pb0 = *(const float4*)Bp0;
    float4 pb1 = *(const float4*)Bp1;

    for (int c0 = 0; c0 < CD; c0 += 16) {
        *(float4*)&As[ka][va]   = pa;
        *(float4*)&Bs[kb0][vb0] = pb0;
        *(float4*)&Bs[kb1][vb1] = pb1;
        __syncthreads();
        if (c0 + 16 < CD) {        // prefetch next K-tile (LDG overlaps compute)
            pa  = *(const float4*)(Ap  + (size_t)(c0 + 16) * HW);
            pb0 = *(const float4*)(Bp0 + (size_t)(c0 + 16) * HW);
            pb1 = *(const float4*)(Bp1 + (size_t)(c0 + 16) * HW);
        }
        #pragma unroll
        for (int kk = 0; kk < 16; kk++) {
            u64 a[5], b[5];
            #pragma unroll
            for (int r = 0; r < 5; r++) {
                float av = As[kk][r * 20 + ty];
                a[r] = pack2(av, av);
            }
            #pragma unroll
            for (int s = 0; s < 5; s++)
                b[s] = *(const u64*)&Bs[kk][tx * 10 + 2 * s];
            #pragma unroll
            for (int r = 0; r < 5; r++)
                #pragma unroll
                for (int s = 0; s < 5; s++) fma2(acc[r][s], a[r], b[s]);
        }
        __syncthreads();
    }

    int b = lb & 1, l = lb >> 1;
    const float* iq = invn + (size_t)lb * HW;
    const float* is = invn + NLB * HW + (size_t)lb * HW;
    float* cp = corr + (size_t)(b * LCH + l) * HW * HW;
    #pragma unroll
    for (int r = 0; r < 5; r++) {
        int ij = ij0 + r * 20 + ty;
        float sq = iq[ij];
        #pragma unroll
        for (int s = 0; s < 5; s++) {
            int col = km0 + tx * 10 + 2 * s;
            float2 isv = *(const float2*)&is[col];
            float lo, hi;
            unpack2(acc[r][s], lo, hi);
            float2 o;
            o.x = lo * sq * isv.x;
            o.y = hi * sq * isv.y;
            *(float2*)&cp[(size_t)ij * HW + col] = o;
        }
    }
}

// ---------------- 4D conv layer (3x3x3x3, pad 1, relu), FFMA2 ----------------
// Block per (bb,i,j), bb in [0,4). Thread = (co, PK x PM patch), PM even.
template <int CIN, int COUT, int PK, int PM>
__global__ void __launch_bounds__(400 / (PK * PM) * COUT) conv4d_k(
        const float* __restrict__ x, const float* __restrict__ wt,
        float* __restrict__ y) {
    constexpr int NPATCH = 400 / (PK * PM);
    constexpr int NT     = NPATCH * COUT;
    constexpr int NPM    = 20 / PM;
    constexpr int PMH    = PM / 2;

    __shared__ float sp[9 * 484];          // 9 padded 22x22 planes for current ci
    __shared__ float wc[81 * COUT];        // weights for current ci

    int bij = blockIdx.x;
    int bb = bij / HW, ij = bij % HW;
    int i = ij / 20, j = ij % 20;
    int tid = threadIdx.x;
    int g   = tid / NPATCH;
    int pid = tid % NPATCH;
    int k0 = (pid / NPM) * PK;
    int m0 = (pid % NPM) * PM;

    for (int t = tid; t < 9 * 484; t += NT) sp[t] = 0.f;   // pad ring stays 0

    u64 acc[PK][PMH];
    #pragma unroll
    for (int pk = 0; pk < PK; pk++)
        #pragma unroll
        for (int h = 0; h < PMH; h++) acc[pk][h] = 0ull;

    for (int ci = 0; ci < CIN; ci++) {
        __syncthreads();
        // stage weights for this ci
        for (int t = tid; t < 81 * COUT; t += NT) {
            int dijtap = t / COUT, co = t % COUT;
            wc[t] = wt[((size_t)co * CIN + ci) * 81 + dijtap];
        }
        // stage 9 neighbor planes, float2 granularity
        for (int t = tid; t < 9 * 200; t += NT) {
            int p = t / 200, rem2 = t % 200;
            int di = p / 3, dj = p % 3;
            int ii = i + di - 1, jj = j + dj - 1;
            int r = rem2 / 10, c2 = (rem2 % 10) * 2;
            float2 v = make_float2(0.f, 0.f);
            if (((unsigned)ii < 20u) && ((unsigned)jj < 20u))
                v = *(const float2*)&x[((size_t)(bb * CIN + ci) * 400 + ii * 20 + jj) * 400
                                       + r * 20 + c2];
            float* dst = &sp[p * 484 + (r + 1) * 22 + (c2 + 1)];
            dst[0] = v.x;
            dst[1] = v.y;
        }
        __syncthreads();

        #pragma unroll
        for (int dij = 0; dij < 9; dij++) {
            const float* P  = sp + dij * 484 + k0 * 22 + m0;
            const float* wp = wc + dij * 9 * COUT + g;
            u64 w2[9];
            #pragma unroll
            for (int t = 0; t < 9; t++) {
                float w = wp[t * COUT];
                w2[t] = pack2(w, w);
            }
            #pragma unroll
            for (int r = 0; r < PK + 2; r++) {
                float xr[PM + 2];
                #pragma unroll
                for (int h = 0; h < (PM + 2) / 2; h++) {
                    float2 v = *(const float2*)&P[r * 22 + 2 * h];
                    xr[2 * h] = v.x;
                    xr[2 * h + 1] = v.y;
                }
                u64 q[PM + 1];
                #pragma unroll
                for (int d = 0; d < PM + 1; d++) q[d] = pack2(xr[d], xr[d + 1]);
                #pragma unroll
                for (int dk = 0; dk < 3; dk++) {
                    int pk = r - dk;
                    if (pk < 0 || pk >= PK) continue;
                    #pragma unroll
                    for (int dm = 0; dm < 3; dm++)
                        #pragma unroll
                        for (int h = 0; h < PMH; h++)
                            fma2(acc[pk][h], q[2 * h + dm], w2[dk * 3 + dm]);
                }
            }
        }
    }

    float* yp = y + ((size_t)(bb * COUT + g) * 400 + ij) * 400;
    #pragma unroll
    for (int pk = 0; pk < PK; pk++)
        #pragma unroll
        for (int h = 0; h < PMH; h++) {
            float lo, hi;
            unpack2(acc[pk][h], lo, hi);
            float2 o;
            o.x = fmaxf(lo, 0.f);
            o.y = fmaxf(hi, 0.f);
            *(float2*)&yp[(k0 + pk) * 20 + m0 + 2 * h] = o;
        }
}

// ---------------- tiled transpose ----------------
__global__ void transpose_k(const float* __restrict__ in, float* __restrict__ out) {
    __shared__ float t[32][33];
    int mtx = blockIdx.z;
    const float* A = in  + (size_t)mtx * HW * HW;
    float*       O = out + (size_t)mtx * HW * HW;
    int x0 = blockIdx.x * 32, y0 = blockIdx.y * 32;
    int tx = threadIdx.x, ty = threadIdx.y;
    #pragma unroll
    for (int r = 0; r < 32; r += 8) {
        int yy = y0 + ty + r, xx = x0 + tx;
        t[ty + r][tx] = (yy < HW && xx < HW) ? A[(size_t)yy * HW + xx] : 0.f;
    }
    __syncthreads();
    #pragma unroll
    for (int r = 0; r < 32; r += 8) {
        int yy = x0 + ty + r, xx = y0 + tx;
        if (yy < HW && xx < HW) O[(size_t)yy * HW + xx] = t[tx][ty + r];
    }
}

// c4[b][q][s] = a[b][q][s] + bt[b][s][q]
__global__ void addt_k(const float* __restrict__ a, const float* __restrict__ bt,
                       float* __restrict__ o) {
    __shared__ float t[32][33];
    int b = blockIdx.z;
    const float* A  = a  + (size_t)b * HW * HW;
    const float* Bt = bt + (size_t)b * HW * HW;
    float*       O  = o  + (size_t)b * HW * HW;
    int q0 = blockIdx.y * 32, s0 = blockIdx.x * 32;
    int tx = threadIdx.x, ty = threadIdx.y;
    #pragma unroll
    for (int r = 0; r < 32; r += 8) {
        int s = s0 + ty + r, q = q0 + tx;
        t[ty + r][tx] = (s < HW && q < HW) ? Bt[(size_t)s * HW + q] : 0.f;
    }
    __syncthreads();
    #pragma unroll
    for (int r = 0; r < 32; r += 8) {
        int q = q0 + ty + r, s = s0 + tx;
        if (q < HW && s < HW) O[(size_t)q * HW + s] = A[(size_t)q * HW + s] + t[tx][ty + r];
    }
}

// ---------------- softmax ----------------
__global__ void softmax_k(const float* __restrict__ x, float* __restrict__ y) {
    int row = blockIdx.x;
    const float* xr = x + (size_t)row * HW;
    float*       yr = y + (size_t)row * HW;
    __shared__ float sh[HW];
    __shared__ float red[4];
    int tid = threadIdx.x;
    float mx = -3.4e38f;
    for (int i = tid; i < HW; i += 128) {
        float v = xr[i] * TEMP;
        sh[i] = v;
        mx = fmaxf(mx, v);
    }
    #pragma unroll
    for (int o = 16; o; o >>= 1) mx = fmaxf(mx, __shfl_xor_sync(0xffffffffu, mx, o));
    if ((tid & 31) == 0) red[tid >> 5] = mx;
    __syncthreads();
    mx = fmaxf(fmaxf(red[0], red[1]), fmaxf(red[2], red[3]));
    float sum = 0.f;
    for (int i = tid; i < HW; i += 128) {
        float e = expf(sh[i] - mx);
        sh[i] = e;
        sum += e;
    }
    #pragma unroll
    for (int o = 16; o; o >>= 1) sum += __shfl_xor_sync(0xffffffffu, sum, o);
    __syncthreads();
    if ((tid & 31) == 0) red[tid >> 5] = sum;
    __syncthreads();
    float inv = 1.f / (red[0] + red[1] + red[2] + red[3]);
    for (int i = tid; i < HW; i += 128) yr[i] = sh[i] * inv;
}

// ---------------- attention GEMM (NT) ----------------
__global__ void attn_gemm_k(const float* __restrict__ attn, const float* __restrict__ v,
                            float* __restrict__ out) {
    int b = blockIdx.z;
    const float* A = v    + (size_t)b * CH * HW;
    const float* P = attn + (size_t)b * HW * HW;
    int c0 = blockIdx.y * 64, q0 = blockIdx.x * 64;

    __shared__ float As[16][65];
    __shared__ float Ps[16][65];
    int tid = threadIdx.x;
    int tx = tid & 15, ty = tid >> 4;
    float acc[4][4] = {};

    for (int s0 = 0; s0 < HW; s0 += 16) {
        #pragma unroll
        for (int t = tid; t < 1024; t += 256) {
            int row = t >> 4, kk = t & 15;
            int c = c0 + row, q = q0 + row;
            As[kk][row] = (c < CH) ? A[(size_t)c * HW + s0 + kk] : 0.f;
            Ps[kk][row] = (q < HW) ? P[(size_t)q * HW + s0 + kk] : 0.f;
        }
        __syncthreads();
        #pragma unroll
        for (int kk = 0; kk < 16; kk++) {
            float a[4], p[4];
            #pragma unroll
            for (int r = 0; r < 4; r++) { a[r] = As[kk][ty * 4 + r]; p[r] = Ps[kk][tx * 4 + r]; }
            #pragma unroll
            for (int r = 0; r < 4; r++)
                #pragma unroll
                for (int s = 0; s < 4; s++) acc[r][s] += a[r] * p[s];
        }
        __syncthreads();
    }
    #pragma unroll
    for (int r = 0; r < 4; r++) {
        int c = c0 + ty * 4 + r;
        if (c >= CH) continue;
        #pragma unroll
        for (int s = 0; s < 4; s++) {
            int q = q0 + tx * 4 + s;
            if (q < HW) out[((size_t)b * CH + c) * HW + q] = acc[r][s];
        }
    }
}

// ---------------- final norms + combine ----------------
__global__ void norm2_k(const float* __restrict__ fqin, const float* __restrict__ att,
                        float* __restrict__ nrm) {
    int b = blockIdx.x, z = blockIdx.y;
    const float* x = (z ? att : fqin) + (size_t)b * CH * HW + threadIdx.x;
    float s = 0.f;
    #pragma unroll 8
    for (int c = 0; c < CH; c++) {
        float v = x[(size_t)c * HW];
        s += v * v;
    }
    nrm[(z * BS + b) * HW + threadIdx.x] = 1.f / fmaxf(sqrtf(s), 1e-12f);
}

__global__ void combine_k(const float* __restrict__ fqin, const float* __restrict__ att,
                          const float* __restrict__ nrm, float* __restrict__ out) {
    int idx = blockIdx.x * blockDim.x + threadIdx.x;
    if (idx >= BS * CH * HW) return;
    int b = idx / (CH * HW);
    int pos = idx % HW;
    out[idx] = fqin[idx] * nrm[b * HW + pos] + att[idx] * nrm[(BS + b) * HW + pos] * 0.5f;
}

// ---------------- launch ----------------
extern "C" void kernel_launch(void* const* d_in, const int* in_sizes, int n_in,
                              void* d_out, int out_size) {
    const float* fqf = (const float*)d_in[0];
    const float* fsf = (const float*)d_in[1];
    const float* f_q = (const float*)d_in[2];
    const float* f_s = (const float*)d_in[3];
    const float* w1  = (const float*)d_in[4];
    const float* w2  = (const float*)d_in[5];
    const float* w3  = (const float*)d_in[6];
    float* out = (float*)d_out;

    float *sumsq, *invn, *corrA, *buf1, *buf2, *c4ab, *c4, *attn, *nrm;
    cudaGetSymbolAddress((void**)&sumsq, g_sumsq);
    cudaGetSymbolAddress((void**)&invn,  g_invn);
    cudaGetSymbolAddress((void**)&corrA, g_corrA);
    cudaGetSymbolAddress((void**)&buf1,  g_buf1);
    cudaGetSymbolAddress((void**)&buf2,  g_buf2);
    cudaGetSymbolAddress((void**)&c4ab,  g_c4ab);
    cudaGetSymbolAddress((void**)&c4,    g_c4);
    cudaGetSymbolAddress((void**)&attn,  g_attn);
    cudaGetSymbolAddress((void**)&nrm,   g_nrm);

    const int NSUM = 2 * NLB * HW;

    // 1. feature L2 norms (folded into GEMM epilogue)
    zero_k<<<(NSUM + 255) / 256, 256>>>(sumsq, NSUM);
    sumsq_k<<<dim3(NLB, 16, 2), 400>>>(fqf, fsf, sumsq);
    invn_k<<<(NSUM + 255) / 256, 256>>>(sumsq, invn, NSUM);

    // 2. correlation tensor (FFMA2, prefetch) into planes [0,18)
    corr_gemm_k<<<dim3(2, 4, NLB), 400>>>(fqf, fsf, invn, corrA);

    // 3. transposed copies into planes [18,36)
    transpose_k<<<dim3(13, 13, NLB), dim3(32, 8)>>>(corrA, corrA + (size_t)NLB * HW * HW);

    // 4. neighborhood consensus — both branches as batch dim 4 (FFMA2)
    conv4d_k<9, 10, 5, 4><<<4 * HW, 200>>>(corrA, w1, buf1);
    conv4d_k<10, 10, 5, 4><<<4 * HW, 200>>>(buf1, w2, buf2);
    conv4d_k<10, 1, 1, 2><<<4 * HW, 200>>>(buf2, w3, c4ab);

    // 5. combine branches (B transposed back)
    addt_k<<<dim3(13, 13, BS), dim3(32, 8)>>>(c4ab, c4ab + 2 * HW * HW, c4);

    // 6. softmax + attention
    softmax_k<<<BS * HW, 128>>>(c4, attn);
    attn_gemm_k<<<dim3(7, 4, BS), 256>>>(attn, f_s, out + BS * CH * HW);

    // 7. final L2-norm combine
    norm2_k<<<dim3(BS, 2), 400>>>(f_q, out + BS * CH * HW, nrm);
    combine_k<<<(BS * CH * HW + 255) / 256, 256>>>(f_q, out + BS * CH * HW, nrm, out);
}